// round 14
// baseline (speedup 1.0000x reference)
#include <cuda_runtime.h>

// HOG layer, fully register-resident: Sobel -> mag + comparison-based 9-bin
// orientation hist -> 8x8 mean pool. No shared memory, no atomics, no syncs.
// Input : x (64,1,512,512) fp32. Output: (64, 9*64*64) fp32.
//
// Thread = 4 cols x 8 rows patch (inside ONE 8x8 cell). Block = 128 threads.
// Lanes l / l^1 co-own one cell (two 4-col halves).
//
// R14: pair-split thermometer. Each pixel's (mag, rat) is exchanged across
// the lane pair (2 shfl.xor); EVEN lanes evaluate thresholds k=1..4 for both
// pixels, ODD lanes k=5..8. Per-pixel binning: 17 -> 11 issue slots. The
// pair then holds the full cell's cumulative sums split as:
//   even: C0', C1..C4   odd: C0', C5..C8
// Bin reconstruction (bin_b = C_{b-1} - C_{b+1}) needs only 3 epilogue shfls.

#define ORI 9

__device__ __forceinline__ float fsqrt_approx(float v) {
    float y;
    asm("sqrt.approx.f32 %0, %1;" : "=f"(y) : "f"(v));
    return y;
}

struct RowTH { float t[4]; float h[4]; };

__device__ __forceinline__ RowTH row_filter(float lf, float4 v, float rt) {
    RowTH o;
    o.t[0] = lf  - v.y;  o.h[0] = fmaf(2.f, v.x, lf)  + v.y;
    o.t[1] = v.x - v.z;  o.h[1] = fmaf(2.f, v.y, v.x) + v.z;
    o.t[2] = v.y - v.w;  o.h[2] = fmaf(2.f, v.z, v.y) + v.w;
    o.t[3] = v.z - rt;   o.h[3] = fmaf(2.f, v.w, v.z) + rt;
    return o;
}

__device__ __forceinline__ RowTH load_row(const float* __restrict__ rp,
                                          bool leftEdge, bool rightEdge) {
    float4 v = *reinterpret_cast<const float4*>(rp);
    float lf = leftEdge  ? 0.f : __ldg(rp - 1);
    float rt = rightEdge ? 0.f : __ldg(rp + 4);
    return row_filter(lf, v, rt);
}

__device__ __forceinline__ RowTH load_row_maybe(const float* __restrict__ rp,
                                                bool valid,
                                                bool leftEdge, bool rightEdge) {
    float4 v = make_float4(0.f, 0.f, 0.f, 0.f);
    float lf = 0.f, rt = 0.f;
    if (valid) {
        v = *reinterpret_cast<const float4*>(rp);
        if (!leftEdge)  lf = __ldg(rp - 1);
        if (!rightEdge) rt = __ldg(rp + 4);
    }
    return row_filter(lf, v, rt);
}

// 4 own pixels: compute (mag, rat), exchange with partner lane, apply this
// lane's 4 thresholds to both own and partner pixels.
__device__ __forceinline__ void bin4pair(const RowTH& a, const RowTH& b,
                                         const RowTH& c,
                                         float T1, float T2, float T3, float T4,
                                         float& C0, float& CA, float& CB,
                                         float& CC, float& CD) {
    float mag[4], rat[4];
    #pragma unroll
    for (int i = 0; i < 4; i++) {
        float gx = fmaf(2.f, b.t[i], a.t[i]) + c.t[i];
        float gy = a.h[i] - c.h[i];
        float r2 = fmaf(gx, gx, gy * gy);
        mag[i] = fsqrt_approx(r2);           // sqrt.approx(0) == 0
        rat[i] = __fdividef(gy, gx);         // cot(theta); +-inf at gx==0
    }
    #pragma unroll
    for (int i = 0; i < 4; i++) {
        float magp = __shfl_xor_sync(0xffffffffu, mag[i], 1);
        float ratp = __shfl_xor_sync(0xffffffffu, rat[i], 1);

        C0 += mag[i];
        if (rat[i] <= T1) CA += mag[i];
        if (rat[i] <= T2) CB += mag[i];
        if (rat[i] <= T3) CC += mag[i];
        if (rat[i] <= T4) CD += mag[i];
        if (ratp   <= T1) CA += magp;
        if (ratp   <= T2) CB += magp;
        if (ratp   <= T3) CC += magp;
        if (ratp   <= T4) CD += magp;
    }
}

__global__ __launch_bounds__(128, 8) void hog_kernel(const float* __restrict__ x,
                                                     float* __restrict__ out)
{
    const int n    = blockIdx.z;
    const int row0 = blockIdx.y * 64;
    const int col0 = blockIdx.x * 64;
    const int tid  = threadIdx.x;
    const int cg   = tid & 15;        // col-group (4 cols each)
    const int rg   = tid >> 4;        // row-group (8 rows each)

    const int c0 = col0 + cg * 4;
    const int r0 = row0 + rg * 8;     // r0 in [0, 504]

    const float* __restrict__ img = x + (size_t)n * (512 * 512);
    const float* __restrict__ rp0 = img + r0 * 512 + c0;

    const bool leftEdge  = (c0 == 0);
    const bool rightEdge = (c0 == 508);
    const bool topOK     = (r0 != 0);
    const bool botOK     = (r0 != 504);
    const bool odd       = (cg & 1);

    // cot(k*pi/9), k = 1..8 (strictly decreasing). Even lanes: k=1..4,
    // odd lanes: k=5..8. Selected once -> loop is lane-uniform.
    const float T1 = odd ? -0.1763269807084650f :  2.7474774194546225f;
    const float T2 = odd ? -0.5773502691896257f :  1.1917535925942100f;
    const float T3 = odd ? -1.1917535925942100f :  0.5773502691896258f;
    const float T4 = odd ? -2.7474774194546230f :  0.1763269807084650f;

    float C0 = 0.f, CA = 0.f, CB = 0.f, CC = 0.f, CD = 0.f;

    RowTH a = load_row_maybe(rp0 - 512, topOK, leftEdge, rightEdge);
    RowTH b = load_row(rp0, leftEdge, rightEdge);

    #pragma unroll
    for (int s = 0; s < 7; s++) {
        RowTH c = load_row(rp0 + (s + 1) * 512, leftEdge, rightEdge);
        bin4pair(a, b, c, T1, T2, T3, T4, C0, CA, CB, CC, CD);
        a = b; b = c;
    }
    {   // last step: row r0+8 may be out of bounds
        RowTH c = load_row_maybe(rp0 + 8 * 512, botOK, leftEdge, rightEdge);
        bin4pair(a, b, c, T1, T2, T3, T4, C0, CA, CB, CC, CD);
    }

    // ---- epilogue: the pair holds the full cell's thermometer sums ----
    // C0 split across lanes -> sum it
    C0 += __shfl_xor_sync(0xffffffffu, C0, 1);
    // even lane: CA..CD = C1..C4; odd lane: CA..CD = C5..C8
    float X = __shfl_xor_sync(0xffffffffu, CD, 1);  // even<-C8, odd<-C4
    float Y = __shfl_xor_sync(0xffffffffu, CA, 1);  // even<-C5, odd<-C1(unused)

    const int ch = (row0 >> 3) + rg;
    const int cw = (col0 >> 3) + (cg >> 1);
    float* obase = out + (size_t)n * (ORI * 64 * 64) + ch * 64 + cw;

    if (!odd) {
        // bins 0..4:  b0=C0-C1+C8, b1=C0-C2, b2=C1-C3, b3=C2-C4, b4=C3-C5
        obase[0 * 4096] = (C0 - CA + X) * (1.0f / 64.0f);
        obase[1 * 4096] = (C0 - CB)     * (1.0f / 64.0f);
        obase[2 * 4096] = (CA - CC)     * (1.0f / 64.0f);
        obase[3 * 4096] = (CB - CD)     * (1.0f / 64.0f);
        obase[4 * 4096] = (CC - Y)      * (1.0f / 64.0f);
    } else {
        // bins 5..8:  b5=C4-C6, b6=C5-C7, b7=C6-C8, b8=C7
        obase[5 * 4096] = (X  - CB)     * (1.0f / 64.0f);
        obase[6 * 4096] = (CA - CC)     * (1.0f / 64.0f);
        obase[7 * 4096] = (CB - CD)     * (1.0f / 64.0f);
        obase[8 * 4096] = CC            * (1.0f / 64.0f);
    }
}

extern "C" void kernel_launch(void* const* d_in, const int* in_sizes, int n_in,
                              void* d_out, int out_size)
{
    const float* x   = (const float*)d_in[0];
    float*       out = (float*)d_out;

    dim3 grid(512 / 64, 512 / 64, 64);
    hog_kernel<<<grid, 128>>>(x, out);
}

// round 15
// speedup vs baseline: 1.0479x; 1.0479x over previous
#include <cuda_runtime.h>

// HOG layer, fully register-resident: Sobel -> mag + comparison-based 9-bin
// orientation hist -> 8x8 mean pool. No shared memory, no atomics, no syncs.
// Input : x (64,1,512,512) fp32. Output: (64, 9*64*64) fp32.
//
// Thread = 4 cols x 8 rows patch (inside ONE 8x8 cell). Block = 128 threads
// = 16 col-groups (64 cols) x 8 row-groups (64 rows). Lane l and l^1 cover
// the two column-halves of the same cell -> cell reduce = one shfl.xor(1).
//
// Bin math: bin = floor(9*atan2(gx,gy)/pi) mod 9 depends only on
// cot(theta) = gy/gx; monotone predicates p_k = [rat <= cot(k*pi/9)] give
// cumulative sums C_k; bins recovered via bin_b = C_{b-1} - C_{b+1}
// (bin0 = C0 - C1 + C8, bin8 = C7).
//
// R15 = R8 with each thermometer accumulate forced to FSET (1.0f/0.0f into a
// register) + FFMA: 2 fma-pipe ops per threshold, no predicate/FSEL path.
// (R8/R11 lowering measured as ~3 ops split across fma+alu.)
// Bit-exact vs R8: fma(1.0,mag,C)==C+mag, fma(0.0,mag,C)==C.

#define ORI 9

__device__ __forceinline__ float fsqrt_approx(float v) {
    float y;
    asm("sqrt.approx.f32 %0, %1;" : "=f"(y) : "f"(v));
    return y;
}

// C += mag * (rat <= T ? 1.0f : 0.0f) via set.le + fma (no predicated flow).
#define ACC_SETFMA(Cref, rat, Tconst, mag)                                    \
    asm("{ .reg .f32 m; set.le.f32.f32 m, %1, %2; fma.rn.f32 %0, m, %3, %0; }"\
        : "+f"(Cref) : "f"(rat), "f"(Tconst), "f"(mag))

struct RowTH { float t[4]; float h[4]; };

__device__ __forceinline__ RowTH row_filter(float lf, float4 v, float rt) {
    RowTH o;
    o.t[0] = lf  - v.y;  o.h[0] = fmaf(2.f, v.x, lf)  + v.y;
    o.t[1] = v.x - v.z;  o.h[1] = fmaf(2.f, v.y, v.x) + v.z;
    o.t[2] = v.y - v.w;  o.h[2] = fmaf(2.f, v.z, v.y) + v.w;
    o.t[3] = v.z - rt;   o.h[3] = fmaf(2.f, v.w, v.z) + rt;
    return o;
}

// Unconditional row load (row known in-bounds). Edge predicates are
// loop-invariant so their zero else-values hoist out of the row loop.
__device__ __forceinline__ RowTH load_row(const float* __restrict__ rp,
                                          bool leftEdge, bool rightEdge) {
    float4 v = *reinterpret_cast<const float4*>(rp);
    float lf = leftEdge  ? 0.f : __ldg(rp - 1);
    float rt = rightEdge ? 0.f : __ldg(rp + 4);
    return row_filter(lf, v, rt);
}

// Row load that may be fully out of bounds (zero row). Used twice per thread.
__device__ __forceinline__ RowTH load_row_maybe(const float* __restrict__ rp,
                                                bool valid,
                                                bool leftEdge, bool rightEdge) {
    float4 v = make_float4(0.f, 0.f, 0.f, 0.f);
    float lf = 0.f, rt = 0.f;
    if (valid) {
        v = *reinterpret_cast<const float4*>(rp);
        if (!leftEdge)  lf = __ldg(rp - 1);
        if (!rightEdge) rt = __ldg(rp + 4);
    }
    return row_filter(lf, v, rt);
}

// Per-pixel binning core: accumulate cumulative sums C[0..8].
__device__ __forceinline__ void bin4(const RowTH& a, const RowTH& b,
                                     const RowTH& c, float* C) {
    #pragma unroll
    for (int i = 0; i < 4; i++) {
        float gx = fmaf(2.f, b.t[i], a.t[i]) + c.t[i];
        float gy = a.h[i] - c.h[i];

        float r2  = fmaf(gx, gx, gy * gy);
        float mag = fsqrt_approx(r2);          // sqrt.approx(0) == 0
        float rat = __fdividef(gy, gx);        // cot(theta); +-inf at gx==0

        C[0] += mag;
        // cot(k*pi/9), k = 1..8 (strictly decreasing), as immediates
        ACC_SETFMA(C[1], rat,  2.7474774194546225f, mag);
        ACC_SETFMA(C[2], rat,  1.1917535925942100f, mag);
        ACC_SETFMA(C[3], rat,  0.5773502691896258f, mag);
        ACC_SETFMA(C[4], rat,  0.1763269807084650f, mag);
        ACC_SETFMA(C[5], rat, -0.1763269807084650f, mag);
        ACC_SETFMA(C[6], rat, -0.5773502691896257f, mag);
        ACC_SETFMA(C[7], rat, -1.1917535925942100f, mag);
        ACC_SETFMA(C[8], rat, -2.7474774194546230f, mag);
    }
}

__global__ __launch_bounds__(128, 8) void hog_kernel(const float* __restrict__ x,
                                                     float* __restrict__ out)
{
    const int n    = blockIdx.z;
    const int row0 = blockIdx.y * 64;
    const int col0 = blockIdx.x * 64;
    const int tid  = threadIdx.x;
    const int cg   = tid & 15;        // col-group (4 cols each)
    const int rg   = tid >> 4;        // row-group (8 rows each)

    const int c0 = col0 + cg * 4;     // first output col of this thread
    const int r0 = row0 + rg * 8;     // first output row; r0 in [0, 504]

    const float* __restrict__ img = x + (size_t)n * (512 * 512);
    const float* __restrict__ rp0 = img + r0 * 512 + c0;

    const bool leftEdge  = (c0 == 0);
    const bool rightEdge = (c0 == 508);
    const bool topOK     = (r0 != 0);     // row r0-1 valid?
    const bool botOK     = (r0 != 504);   // row r0+8 valid?

    float C[9];
    #pragma unroll
    for (int b = 0; b < 9; b++) C[b] = 0.0f;

    RowTH a = load_row_maybe(rp0 - 512, topOK, leftEdge, rightEdge);
    RowTH b = load_row(rp0, leftEdge, rightEdge);

    #pragma unroll
    for (int s = 0; s < 7; s++) {
        RowTH c = load_row(rp0 + (s + 1) * 512, leftEdge, rightEdge);
        bin4(a, b, c, C);
        a = b; b = c;
    }
    {   // last step: row r0+8 may be out of bounds
        RowTH c = load_row_maybe(rp0 + 8 * 512, botOK, leftEdge, rightEdge);
        bin4(a, b, c, C);
    }

    // ---- cell reduction: partner lane (lane^1) holds the other 4 columns ----
    #pragma unroll
    for (int q = 0; q < 9; q++)
        C[q] += __shfl_xor_sync(0xffffffffu, C[q], 1);

    // ---- recover bins, write pooled output (split 9 bins across the pair) ----
    const int ch = (row0 >> 3) + rg;
    const int cw = (col0 >> 3) + (cg >> 1);
    float* obase = out + (size_t)n * (ORI * 64 * 64) + ch * 64 + cw;

    float bins[9];
    bins[0] = C[0] - C[1] + C[8];
    #pragma unroll
    for (int q = 1; q < 8; q++) bins[q] = C[q - 1] - C[q + 1];
    bins[8] = C[7];

    if ((cg & 1) == 0) {
        #pragma unroll
        for (int q = 0; q < 5; q++)
            obase[q * 4096] = bins[q] * (1.0f / 64.0f);
    } else {
        #pragma unroll
        for (int q = 5; q < 9; q++)
            obase[q * 4096] = bins[q] * (1.0f / 64.0f);
    }
}

extern "C" void kernel_launch(void* const* d_in, const int* in_sizes, int n_in,
                              void* d_out, int out_size)
{
    const float* x   = (const float*)d_in[0];
    float*       out = (float*)d_out;

    dim3 grid(512 / 64, 512 / 64, 64);
    hog_kernel<<<grid, 128>>>(x, out);
}